// round 8
// baseline (speedup 1.0000x reference)
#include <cuda_runtime.h>

// LFQ quantizer — sparse factorized softmax, single kernel.
// N = 8192 samples, D = 14, K = 16384, T = 0.01.
//
// softmax factorizes: p_j = prod_d sigmoid(400 x_d c_jd).
// u_d = e^{-400|x_d|} > 1e-8 only for |x_d| < 0.046 (~3.7%/dim) -> each
// sample's mass lives on ~1.7 codes: enumerate subsets of the soft-dim mask,
// ~14K scattered atomics total into g_M.
// sample_entropy = sum_d binary_entropy(sigmoid(400 x_d)) (factorized, exact).
//
// 32 blocks x 256 threads (fewer barrier arrivals, better latency hiding).
// Phase 1: coalesced elementwise + per-sample scatter. Grid barrier with
// nanosleep backoff. Phase 2: distributed entropy (512 codes/block) + re-zero.
// Last-ticket block writes 4 scalars and resets state (graph-replay safe).

#define DIMS 14
#define NCODES 16384
#define NB 32
#define BTH 256
#define SPB 256                // samples per block
#define EPB (SPB * DIMS)       // 3584 floats per block
#define E4PB (EPB / 4)         // 896 float4 per block
#define CPB (NCODES / NB)      // 512 codes per block in phase 2
#define UTH 1e-8f

__device__ float g_M[NCODES];            // per-code prob sums (zeroed each run)
__device__ float g_sC, g_sH, g_sE;       // commit / sampleH / avgH accumulators
__device__ unsigned g_bar, g_go, g_ticket;

__global__ __launch_bounds__(BTH) void lfq_fused(const float* __restrict__ x,
                                                 float* __restrict__ out,
                                                 int qn, int out_size,
                                                 float inv_n) {
    __shared__ unsigned us[EPB];   // bit31 = quantized bit, bits30..0 = u (exact)
    __shared__ float w1[8], w2[8];

    const int tid = threadIdx.x;
    const int lane = tid & 31, wid = tid >> 5;
    const float4* x4 = (const float4*)x + blockIdx.x * E4PB;
    float4* o4 = (float4*)out + blockIdx.x * E4PB;

    // ========== phase 1a: elementwise, fully coalesced float4 ==========
    float commit = 0.f, h = 0.f;
    #pragma unroll
    for (int k = 0; k < 4; ++k) {
        int i = tid + k * BTH;
        if (i < E4PB) {
            float4 xv = x4[i];
            float vx[4] = {xv.x, xv.y, xv.z, xv.w};
            float qq[4];
            #pragma unroll
            for (int j = 0; j < 4; ++j) {
                float v = vx[j];
                bool pos = (v > 0.f);
                float qz = pos ? 1.f : -1.f;
                qq[j] = qz;
                float dq = v - qz;
                commit += dq * dq;
                float t = fabsf(400.f * v);
                float u = __expf(-t);                    // flip ratio e^{-|z|}
                float inv = 1.f / (1.f + u);
                h += (u > 1e-4f) ? (__logf(1.f + u) + t * u * inv)
                                 : u * (1.f + t);        // 1st order, err ~ u^2
                us[4 * i + j] = __float_as_uint(u) | (pos ? 0x80000000u : 0u);
            }
            float4 q; q.x = qq[0]; q.y = qq[1]; q.z = qq[2]; q.w = qq[3];
            o4[i] = q;                                   // coalesced STG.128
        }
    }
    __syncthreads();

    // ========== phase 1b: per-sample sparse scatter (1 thread/sample) ==========
    {
        const unsigned* up = &us[tid * DIMS];
        float p_main = 1.f;
        int j_main = 0;
        unsigned soft = 0;
        #pragma unroll
        for (int d = 0; d < DIMS; ++d) {
            unsigned w = up[d];
            float u = __uint_as_float(w & 0x7fffffffu);
            if (w >> 31) j_main |= (1 << d);
            p_main *= 1.f / (1.f + u);
            if (u > UTH) soft |= (1u << d);
        }
        unsigned m = 0;
        do {                                             // subsets of `soft`
            float p = p_main;
            unsigned r = m;
            while (r) {
                int d = __ffs(r) - 1;
                p *= __uint_as_float(up[d] & 0x7fffffffu);
                r &= r - 1;
            }
            atomicAdd(&g_M[j_main ^ (int)m], p);
            m = (m - soft) & soft;
        } while (m);
    }

    // block-reduce commit & sample-entropy (8 warps)
    #pragma unroll
    for (int off = 16; off; off >>= 1) {
        commit += __shfl_down_sync(0xffffffffu, commit, off);
        h      += __shfl_down_sync(0xffffffffu, h, off);
    }
    if (lane == 0) { w1[wid] = commit; w2[wid] = h; }

    // ========== grid barrier: 32 arrivals + release flag, backoff poll ==========
    __threadfence();                    // publish g_M atomics & partials
    __syncthreads();
    if (tid == 0) {
        float cs = 0.f, hs = 0.f;
        #pragma unroll
        for (int w = 0; w < 8; ++w) { cs += w1[w]; hs += w2[w]; }
        atomicAdd(&g_sC, cs);
        atomicAdd(&g_sH, hs);
        __threadfence();
        if (atomicAdd(&g_bar, 1u) == NB - 1) atomicExch(&g_go, 1u);
        while (((volatile unsigned*)&g_go)[0] == 0u) __nanosleep(64);
    }
    __syncthreads();
    __threadfence();                    // acquire for g_M reads below

    // ========== phase 2: distributed entropy over avg_probs + re-zero ==========
    float ea = 0.f;
    const int base = blockIdx.x * CPB;
    #pragma unroll
    for (int k = 0; k < CPB / BTH; ++k) {               // 2 iters, coalesced
        int c = base + k * BTH + tid;
        float v = __ldcg(&g_M[c]);
        g_M[c] = 0.f;                                    // reset for next replay
        if (v != 0.f) {
            float mm = v * inv_n;
            ea -= mm * __logf(mm + 1e-5f);
        }
    }
    #pragma unroll
    for (int off = 16; off; off >>= 1)
        ea += __shfl_down_sync(0xffffffffu, ea, off);
    if (lane == 0) w1[wid] = ea;
    __syncthreads();

    if (tid == 0) {
        float es = 0.f;
        #pragma unroll
        for (int w = 0; w < 8; ++w) es += w1[w];
        atomicAdd(&g_sE, es);
        __threadfence();
        if (atomicAdd(&g_ticket, 1u) == NB - 1) {        // last block finalizes
            __threadfence();
            float samp = __ldcg(&g_sH) * inv_n;
            float avg  = __ldcg(&g_sE);
            float cm   = __ldcg(&g_sC) * inv_n * (1.f / (float)DIMS);
            if (out_size >= qn + 4) {
                out[qn + 0] = samp - avg;                // entropy_aux_loss
                out[qn + 1] = samp;                      // sample_entropy
                out[qn + 2] = avg;                       // avg_entropy
                out[qn + 3] = cm;                        // commit_loss
            }
            g_sC = 0.f; g_sH = 0.f; g_sE = 0.f;          // reset for next replay
            g_bar = 0u; g_ticket = 0u;
            atomicExch(&g_go, 0u);
        }
    }
}

extern "C" void kernel_launch(void* const* d_in, const int* in_sizes, int n_in,
                              void* d_out, int out_size) {
    const float* x = (const float*)d_in[0];
    float* out = (float*)d_out;
    int qn = in_sizes[0];                   // 8*1024*14 = 114688
    float inv_n = 1.f / (float)(qn / DIMS); // 1/8192

    lfq_fused<<<NB, BTH>>>(x, out, qn, out_size, inv_n);
}

// round 9
// speedup vs baseline: 1.3655x; 1.3655x over previous
#include <cuda_runtime.h>

// LFQ quantizer — sparse factorized softmax, single kernel, minimal serial chain.
// N = 8192 samples, D = 14, K = 16384, T = 0.01.
//
// softmax factorizes: p_j = prod_d sigmoid(400 x_d c_jd).
// u_d = e^{-400|x_d|} > 1e-4 only for |x_d| < 0.023 (~1.8%/dim) -> each
// sample's mass lives on ~1.3 codes: enumerate subsets of the soft-dim mask
// (dropped flip mass ~3e-6/sample -> entropy error ~3e-5 abs, well in tol).
// sample_entropy = sum_d binary_entropy(sigmoid(400 x_d)) (factorized).
//
// 32 blocks x 256 threads. Phase 1: coalesced elementwise + sparse scatter.
// Grid barrier: ONE counter atomic per block (arrive-first, partials stored
// while waiting, no contended scalar atomics anywhere). Phase 2: distributed
// entropy (512 codes/block) + re-zero. Last-ticket block sums the 32 partial
// slots with a warp, writes 4 scalars, resets counters (graph-replay safe).

#define DIMS 14
#define NCODES 16384
#define NB 32
#define BTH 256
#define SPB 256                // samples per block
#define EPB (SPB * DIMS)       // 3584 floats per block
#define E4PB (EPB / 4)         // 896 float4 per block
#define CPB (NCODES / NB)      // 512 codes per block in phase 2
#define UTH 1e-4f

__device__ float g_M[NCODES];                  // per-code prob sums (zeroed each run)
__device__ float g_cP[NB], g_hP[NB], g_eP[NB]; // per-block partial slots (STG only)
__device__ unsigned g_bar, g_ticket;

__global__ __launch_bounds__(BTH) void lfq_fused(const float* __restrict__ x,
                                                 float* __restrict__ out,
                                                 int qn, int out_size,
                                                 float inv_n) {
    __shared__ unsigned us[EPB];   // bit31 = quantized bit, bits30..0 = u (exact)
    __shared__ float w1[8], w2[8];
    __shared__ int s_last;

    const int tid = threadIdx.x;
    const int lane = tid & 31, wid = tid >> 5;
    const int bid = blockIdx.x;
    const float4* x4 = (const float4*)x + bid * E4PB;
    float4* o4 = (float4*)out + bid * E4PB;

    // ========== phase 1a: elementwise, fully coalesced float4 ==========
    float commit = 0.f, h = 0.f;
    #pragma unroll
    for (int k = 0; k < 4; ++k) {
        int i = tid + k * BTH;
        if (i < E4PB) {
            float4 xv = x4[i];
            float vx[4] = {xv.x, xv.y, xv.z, xv.w};
            float qq[4];
            #pragma unroll
            for (int j = 0; j < 4; ++j) {
                float v = vx[j];
                bool pos = (v > 0.f);
                float qz = pos ? 1.f : -1.f;
                qq[j] = qz;
                float dq = v - qz;
                commit += dq * dq;
                float t = fabsf(400.f * v);
                float u = __expf(-t);                    // flip ratio e^{-|z|}
                float inv = 1.f / (1.f + u);
                h += (u > 1e-4f) ? (__logf(1.f + u) + t * u * inv)
                                 : u * (1.f + t);        // 1st order, err ~ u^2
                us[4 * i + j] = __float_as_uint(u) | (pos ? 0x80000000u : 0u);
            }
            float4 q; q.x = qq[0]; q.y = qq[1]; q.z = qq[2]; q.w = qq[3];
            o4[i] = q;                                   // coalesced STG.128
        }
    }
    __syncthreads();

    // ========== phase 1b: per-sample sparse scatter (1 thread/sample) ==========
    {
        const unsigned* up = &us[tid * DIMS];
        float p_main = 1.f;
        int j_main = 0;
        unsigned soft = 0;
        #pragma unroll
        for (int d = 0; d < DIMS; ++d) {
            unsigned w = up[d];
            float u = __uint_as_float(w & 0x7fffffffu);
            if (w >> 31) j_main |= (1 << d);
            p_main *= 1.f / (1.f + u);                   // exact normalization
            if (u > UTH) soft |= (1u << d);              // enumerate only these
        }
        unsigned m = 0;
        do {                                             // subsets of `soft`
            float p = p_main;
            unsigned r = m;
            while (r) {
                int d = __ffs(r) - 1;
                p *= __uint_as_float(up[d] & 0x7fffffffu);
                r &= r - 1;
            }
            atomicAdd(&g_M[j_main ^ (int)m], p);
            m = (m - soft) & soft;
        } while (m);
    }

    // block-reduce commit & sample-entropy (registers/smem only)
    #pragma unroll
    for (int off = 16; off; off >>= 1) {
        commit += __shfl_down_sync(0xffffffffu, commit, off);
        h      += __shfl_down_sync(0xffffffffu, h, off);
    }
    if (lane == 0) { w1[wid] = commit; w2[wid] = h; }

    // ========== grid barrier: arrive first, store partials while waiting ==========
    __threadfence();                     // publish g_M atomics
    __syncthreads();                     // w1/w2 ready
    if (tid == 0) {
        unsigned t = atomicAdd(&g_bar, 1u);              // arrival ASAP
        float cs = 0.f, hs = 0.f;
        #pragma unroll
        for (int w = 0; w < 8; ++w) { cs += w1[w]; hs += w2[w]; }
        g_cP[bid] = cs;                                  // plain STG, no contention
        g_hP[bid] = hs;                                  // (visibility via ticket fence)
        if (t != NB - 1)
            while (((volatile unsigned*)&g_bar)[0] < NB) __nanosleep(32);
    }
    __syncthreads();
    __threadfence();                     // acquire for g_M reads below

    // ========== phase 2: distributed entropy over avg_probs + re-zero ==========
    float ea = 0.f;
    const int base = bid * CPB;
    #pragma unroll
    for (int k = 0; k < CPB / BTH; ++k) {                // 2 iters, coalesced
        int c = base + k * BTH + tid;
        float v = __ldcg(&g_M[c]);
        g_M[c] = 0.f;                                    // reset for next replay
        float mm = v * inv_n;
        ea -= mm * __logf(mm + 1e-5f);                   // mm==0 -> exactly 0
    }
    #pragma unroll
    for (int off = 16; off; off >>= 1)
        ea += __shfl_down_sync(0xffffffffu, ea, off);
    if (lane == 0) w1[wid] = ea;
    __syncthreads();

    if (tid == 0) {
        float es = 0.f;
        #pragma unroll
        for (int w = 0; w < 8; ++w) es += w1[w];
        g_eP[bid] = es;                                  // plain STG
        __threadfence();                                 // release partials
        unsigned tk = atomicAdd(&g_ticket, 1u);
        s_last = (tk == NB - 1);
    }
    __syncthreads();
    if (!s_last) return;

    // ========== last block: sum 32 partial slots, write scalars, reset ==========
    __threadfence();                     // acquire all blocks' partial STGs
    if (wid == 0) {
        float cs = g_cP[lane];           // NB == 32: one value per lane
        float hs = g_hP[lane];
        float es = g_eP[lane];
        #pragma unroll
        for (int off = 16; off; off >>= 1) {
            cs += __shfl_down_sync(0xffffffffu, cs, off);
            hs += __shfl_down_sync(0xffffffffu, hs, off);
            es += __shfl_down_sync(0xffffffffu, es, off);
        }
        if (lane == 0) {
            float samp = hs * inv_n;
            float cm = cs * inv_n * (1.f / (float)DIMS);
            if (out_size >= qn + 4) {
                out[qn + 0] = samp - es;                 // entropy_aux_loss
                out[qn + 1] = samp;                      // sample_entropy
                out[qn + 2] = es;                        // avg_entropy
                out[qn + 3] = cm;                        // commit_loss
            }
            g_bar = 0u;                                  // reset for next replay
            g_ticket = 0u;
        }
    }
}

extern "C" void kernel_launch(void* const* d_in, const int* in_sizes, int n_in,
                              void* d_out, int out_size) {
    const float* x = (const float*)d_in[0];
    float* out = (float*)d_out;
    int qn = in_sizes[0];                   // 8*1024*14 = 114688
    float inv_n = 1.f / (float)(qn / DIMS); // 1/8192

    lfq_fused<<<NB, BTH>>>(x, out, qn, out_size, inv_n);
}